// round 10
// baseline (speedup 1.0000x reference)
#include <cuda_runtime.h>
#include <cstddef>

#define M_PTS 100000

// level-0 volume dims (D,H,W)
#define D0v 176
#define H0v 208
#define W0v 176
// level-1
#define D1v 88
#define H1v 104
#define W1v 88
// level-2
#define D2v 44
#define H2v 52
#define W2v 44

// ---------------- static device scratch (no allocations allowed) ----------------
__device__ float g_vol1[D1v * H1v * W1v];
__device__ float g_vol2[D2v * H2v * W2v];
__device__ float g_wct[384 * 128];    // conv_w transposed -> [k][o], K padded to 384
__device__ float g_wlt[128 * 128];    // lfc_w transposed -> [c][o]
__device__ float g_w2t[256 * 512];    // fc2_w transposed -> [k][n]
__device__ float g_w3t[512 * 256];    // fc3_w transposed -> [k][n]
__device__ float g_v[(size_t)M_PTS * 384];    // sampled cubes, padded K=384
__device__ float g_zl[(size_t)M_PTS * 128];   // conv output (pre-lfc), fp32
__device__ float g_z1[(size_t)M_PTS * 256];   // [z_point | z_local]
__device__ float g_z2[(size_t)M_PTS * 512];
__device__ float g_z3[(size_t)M_PTS * 256];

// ---------------- setup kernels (run every launch; deterministic) ----------------
__global__ void pool1_kernel(const float* __restrict__ V) {
    int n = blockIdx.x * blockDim.x + threadIdx.x;
    if (n >= D1v * H1v * W1v) return;
    int xx = n % W1v; int t = n / W1v; int yy = t % H1v; int zz = t / H1v;
    float s = 0.f;
#pragma unroll
    for (int dz = 0; dz < 2; dz++)
#pragma unroll
        for (int dy = 0; dy < 2; dy++)
#pragma unroll
            for (int dx = 0; dx < 2; dx++)
                s = __fadd_rn(s, V[((size_t)(2 * zz + dz) * H0v + (2 * yy + dy)) * W0v + (2 * xx + dx)]);
    g_vol1[n] = __fmul_rn(s, 0.125f);
}

__global__ void pool2_kernel() {
    int n = blockIdx.x * blockDim.x + threadIdx.x;
    if (n >= D2v * H2v * W2v) return;
    int xx = n % W2v; int t = n / W2v; int yy = t % H2v; int zz = t / H2v;
    float s = 0.f;
#pragma unroll
    for (int dz = 0; dz < 2; dz++)
#pragma unroll
        for (int dy = 0; dy < 2; dy++)
#pragma unroll
            for (int dx = 0; dx < 2; dx++)
                s = __fadd_rn(s, g_vol1[((size_t)(2 * zz + dz) * H1v + (2 * yy + dy)) * W1v + (2 * xx + dx)]);
    g_vol2[n] = __fmul_rn(s, 0.125f);
}

__global__ void prep_convw(const float* __restrict__ conv_w) {
    int n = blockIdx.x * blockDim.x + threadIdx.x;   // over 384*128
    if (n >= 384 * 128) return;
    int k = n >> 7, o = n & 127;
    g_wct[n] = (k < 375) ? conv_w[o * 375 + k] : 0.f;
}

__global__ void prep_lfcw(const float* __restrict__ lfc_w) {
    int n = blockIdx.x * blockDim.x + threadIdx.x;   // over 128*128
    if (n >= 128 * 128) return;
    int c = n >> 7, o = n & 127;
    g_wlt[n] = lfc_w[o * 128 + c];
}

__global__ void transpose_w2(const float* __restrict__ fc2_w) {
    int n = blockIdx.x * blockDim.x + threadIdx.x;   // over 512*256
    if (n >= 512 * 256) return;
    int r = n >> 8, c = n & 255;   // fc2_w[r][c], r<512, c<256
    g_w2t[c * 512 + r] = fc2_w[n];
}

__global__ void transpose_w3(const float* __restrict__ fc3_w) {
    int n = blockIdx.x * blockDim.x + threadIdx.x;   // over 256*512
    if (n >= 256 * 512) return;
    int r = n >> 9, c = n & 511;   // fc3_w[r][c], r<256, c<512
    g_w3t[c * 256 + r] = fc3_w[n];
}

// ---------------- sampling kernel: one warp per point, fc1 folded in ----------------
// grid = np.linspace(-K//2, K//2, K), K=5, Python floor div: (-5)//2=-3
//   -> grid = [-3, -1.75, -0.5, 0.75, 2]  (all exact in fp32)
// XLA algebraic-simplifier semantics for the coordinate chain:
//   xq / RESCALE  ->  xq * fl32(1/RESCALE)   [divide-by-constant -> reciprocal mul]
//   fl32(1/fl32(176/208)) == (float)(208.0/176.0)  (verified: both -> mantissa 9913809)
//   axis 1 divides by 1.0 -> removed.
__global__ void sample_kernel(const float* __restrict__ x, const float* __restrict__ V,
                              const float* __restrict__ fc1_w, const float* __restrict__ fc1_b) {
    const int NW = 8;
    __shared__ int   s_xi0[NW][5], s_xi1[NW][5];
    __shared__ int   s_yo0[NW][5], s_yo1[NW][5];
    __shared__ int   s_zo0[NW][5], s_zo1[NW][5];
    __shared__ float s_wx[NW][5], s_wy[NW][5], s_wz[NW][5];

    int w = threadIdx.x >> 5, lane = threadIdx.x & 31;
    int m = blockIdx.x * NW + w;
    if (m >= M_PTS) return;

    float x0 = __ldg(&x[3 * m + 0]);
    float x1 = __ldg(&x[3 * m + 1]);
    float x2 = __ldg(&x[3 * m + 2]);
    const float INV_RESC = (float)(208.0 / 176.0);   // == fl32(1/fl32(176/208))

#pragma unroll
    for (int q = 0; q < 3; q++) {
        const float* vol = (q == 0) ? V : (q == 1 ? g_vol1 : g_vol2);
        int Dd = D0v >> q, Hh = H0v >> q, Ww = W0v >> q;

        if (lane < 15) {
            int a = lane / 5, j = lane % 5;
            float xc = (a == 0) ? x0 : (a == 1 ? x1 : x2);
            int dim = (a == 0) ? Ww : (a == 1 ? Hh : Dd);
            float hi = (float)(dim - 1);
            float halfhi = __fmul_rn(0.5f, hi);            // exact
            float g = -3.0f + 1.25f * (float)j;            // exact
            float shift = __fmul_rn(__fmul_rn(__fdiv_rn(g, 208.0f), 2.0f), (float)(1 << q));
            float xq = __fadd_rn(xc, shift);
            float coords = (a == 1) ? xq : __fmul_rn(xq, INV_RESC);  // XLA reciprocal-mul
            float pix = __fmul_rn(__fadd_rn(coords, 1.0f), halfhi);
            pix = fminf(fmaxf(pix, 0.0f), hi);
            float p0f = floorf(pix);
            int i0 = (int)p0f;
            float fr = __fadd_rn(pix, -p0f);
            int i1 = min(i0 + 1, dim - 1);
            if (a == 0)      { s_xi0[w][j] = i0;           s_xi1[w][j] = i1;           s_wx[w][j] = fr; }
            else if (a == 1) { s_yo0[w][j] = i0 * Ww;      s_yo1[w][j] = i1 * Ww;      s_wy[w][j] = fr; }
            else             { s_zo0[w][j] = i0 * Ww * Hh; s_zo1[w][j] = i1 * Ww * Hh; s_wz[w][j] = fr; }
        }
        __syncwarp();

        float* vout = &g_v[(size_t)m * 384 + q * 125];
        for (int s = lane; s < 125; s += 32) {
            int p0 = s / 25, rr = s % 25, p1 = rr / 5, p2 = rr % 5;
            int ix0 = s_xi0[w][p0], ix1 = s_xi1[w][p0];
            float fx = s_wx[w][p0];
            int yo0 = s_yo0[w][p1], yo1 = s_yo1[w][p1];
            float fy = s_wy[w][p1];
            int zo0 = s_zo0[w][p2], zo1 = s_zo1[w][p2];
            float fz = s_wz[w][p2];
            float ox = __fadd_rn(1.0f, -fx);
            float oy = __fadd_rn(1.0f, -fy);
            float oz = __fadd_rn(1.0f, -fz);
            int b00 = zo0 + yo0, b10 = zo0 + yo1, b01 = zo1 + yo0, b11 = zo1 + yo1;
            float v000 = __ldg(vol + b00 + ix0), v100 = __ldg(vol + b00 + ix1);
            float v010 = __ldg(vol + b10 + ix0), v110 = __ldg(vol + b10 + ix1);
            float v001 = __ldg(vol + b01 + ix0), v101 = __ldg(vol + b01 + ix1);
            float v011 = __ldg(vol + b11 + ix0), v111 = __ldg(vol + b11 + ix1);
            // c = v0*(1-w) + v1*w, literal reference form, no fma contraction
            float c00 = __fadd_rn(__fmul_rn(v000, ox), __fmul_rn(v100, fx));
            float c10 = __fadd_rn(__fmul_rn(v010, ox), __fmul_rn(v110, fx));
            float c01 = __fadd_rn(__fmul_rn(v001, ox), __fmul_rn(v101, fx));
            float c11 = __fadd_rn(__fmul_rn(v011, ox), __fmul_rn(v111, fx));
            float c0 = __fadd_rn(__fmul_rn(c00, oy), __fmul_rn(c10, fy));
            float c1 = __fadd_rn(__fmul_rn(c01, oy), __fmul_rn(c11, fy));
            vout[s] = __fadd_rn(__fmul_rn(c0, oz), __fmul_rn(c1, fz));
        }
        __syncwarp();
    }
    if (lane < 9) g_v[(size_t)m * 384 + 375 + lane] = 0.f;

    // fc1: z_point = leaky_relu(x @ fc1_w^T + fc1_b)
    // GEMM-form: zero-init accumulator, fma-sequential over k
#pragma unroll
    for (int r = 0; r < 4; r++) {
        int o = lane + r * 32;
        float d = __fmul_rn(fc1_w[o * 3 + 0], x0);
        d = fmaf(fc1_w[o * 3 + 1], x1, d);
        d = fmaf(fc1_w[o * 3 + 2], x2, d);
        float z = __fadd_rn(d, fc1_b[o]);
        z = (z >= 0.f) ? z : __fmul_rn(0.2f, z);
        g_z1[(size_t)m * 256 + o] = z;
    }
}

// ---------------- fp32 tiled SGEMM: C[M,N] = A[M,K(lda)] * B[K,N] + bias, opt leaky ----------------
// k-sequential single fp32 accumulator with fma (matches cuBLAS SIMT sgemm order).
template <bool LEAKY>
__global__ void sgemm_kernel(const float* __restrict__ A, const float* __restrict__ B,
                             float* __restrict__ C, const float* __restrict__ bias,
                             int M, int N, int K, int lda, int ldc) {
    __shared__ __align__(16) float As[8][128];
    __shared__ __align__(16) float Bs[8][128];
    int tid = threadIdx.x;                  // 256 threads
    int bm = blockIdx.x, bn = blockIdx.y;

    int rowA = tid >> 1;                    // 0..127
    int colA = (tid & 1) * 4;               // 0 or 4
    int rowB = tid >> 5;                    // 0..7
    int colB = (tid & 31) * 4;

    int gRowA = bm * 128 + rowA;
    const float* Aptr = A + (size_t)gRowA * lda + colA;
    const float* Bptr = B + (size_t)rowB * N + bn * 128 + colB;

    int tx = tid & 15, ty = tid >> 4;
    float acc[8][8];
#pragma unroll
    for (int i = 0; i < 8; i++)
#pragma unroll
        for (int j = 0; j < 8; j++) acc[i][j] = 0.f;

    for (int k0 = 0; k0 < K; k0 += 8) {
        float4 av = make_float4(0.f, 0.f, 0.f, 0.f);
        if (gRowA < M) av = *reinterpret_cast<const float4*>(Aptr + k0);
        As[colA + 0][rowA] = av.x;
        As[colA + 1][rowA] = av.y;
        As[colA + 2][rowA] = av.z;
        As[colA + 3][rowA] = av.w;
        float4 bv = *reinterpret_cast<const float4*>(Bptr + (size_t)k0 * N);
        *reinterpret_cast<float4*>(&Bs[rowB][colB]) = bv;
        __syncthreads();
#pragma unroll
        for (int kk = 0; kk < 8; kk++) {
            float4 a0 = *reinterpret_cast<const float4*>(&As[kk][ty * 8]);
            float4 a1 = *reinterpret_cast<const float4*>(&As[kk][ty * 8 + 4]);
            float4 b0 = *reinterpret_cast<const float4*>(&Bs[kk][tx * 8]);
            float4 b1 = *reinterpret_cast<const float4*>(&Bs[kk][tx * 8 + 4]);
            float a[8] = {a0.x, a0.y, a0.z, a0.w, a1.x, a1.y, a1.z, a1.w};
            float b[8] = {b0.x, b0.y, b0.z, b0.w, b1.x, b1.y, b1.z, b1.w};
#pragma unroll
            for (int i = 0; i < 8; i++)
#pragma unroll
                for (int j = 0; j < 8; j++)
                    acc[i][j] = fmaf(a[i], b[j], acc[i][j]);
        }
        __syncthreads();
    }

#pragma unroll
    for (int i = 0; i < 8; i++) {
        int gr = bm * 128 + ty * 8 + i;
        if (gr >= M) continue;
#pragma unroll
        for (int j = 0; j < 8; j++) {
            int gc = bn * 128 + tx * 8 + j;
            float v = __fadd_rn(acc[i][j], bias[gc]);
            if (LEAKY) v = (v >= 0.f) ? v : __fmul_rn(0.2f, v);
            C[(size_t)gr * ldc + gc] = v;
        }
    }
}

// ---------------- fc4 + ODE update: one thread per point, k-sequential fma ----------------
__global__ void fc4_kernel(const float* __restrict__ xin, float* __restrict__ xout,
                           const float* __restrict__ w4, const float* __restrict__ b4) {
    int m = blockIdx.x * blockDim.x + threadIdx.x;
    if (m >= M_PTS) return;
    const float* z = &g_z3[(size_t)m * 256];
    float s0 = 0.f, s1 = 0.f, s2 = 0.f;
    for (int k = 0; k < 256; k++) {
        float zv = z[k];
        s0 = fmaf(zv, __ldg(&w4[k]), s0);
        s1 = fmaf(zv, __ldg(&w4[256 + k]), s1);
        s2 = fmaf(zv, __ldg(&w4[512 + k]), s2);
    }
    float d0 = __fadd_rn(s0, b4[0]);
    float d1 = __fadd_rn(s1, b4[1]);
    float d2 = __fadd_rn(s2, b4[2]);
    xout[3 * m + 0] = __fadd_rn(xin[3 * m + 0], __fmul_rn(0.2f, d0));
    xout[3 * m + 1] = __fadd_rn(xin[3 * m + 1], __fmul_rn(0.2f, d1));
    xout[3 * m + 2] = __fadd_rn(xin[3 * m + 2], __fmul_rn(0.2f, d2));
}

// ---------------- launch ----------------
extern "C" void kernel_launch(void* const* d_in, const int* in_sizes, int n_in,
                              void* d_out, int out_size) {
    const float* x_in  = (const float*)d_in[0];
    const float* V     = (const float*)d_in[1];
    const float* fc1_w = (const float*)d_in[2];
    const float* fc1_b = (const float*)d_in[3];
    const float* fc2_w = (const float*)d_in[4];
    const float* fc2_b = (const float*)d_in[5];
    const float* fc3_w = (const float*)d_in[6];
    const float* fc3_b = (const float*)d_in[7];
    const float* fc4_w = (const float*)d_in[8];
    const float* fc4_b = (const float*)d_in[9];
    const float* conv_w = (const float*)d_in[10];
    const float* conv_b = (const float*)d_in[11];
    const float* lfc_w  = (const float*)d_in[12];
    const float* lfc_b  = (const float*)d_in[13];
    float* xbuf = (float*)d_out;

    float *p_v, *p_zl, *p_z1, *p_z2, *p_z3, *p_wct, *p_wlt, *p_w2t, *p_w3t;
    cudaGetSymbolAddress((void**)&p_v,   g_v);
    cudaGetSymbolAddress((void**)&p_zl,  g_zl);
    cudaGetSymbolAddress((void**)&p_z1,  g_z1);
    cudaGetSymbolAddress((void**)&p_z2,  g_z2);
    cudaGetSymbolAddress((void**)&p_z3,  g_z3);
    cudaGetSymbolAddress((void**)&p_wct, g_wct);
    cudaGetSymbolAddress((void**)&p_wlt, g_wlt);
    cudaGetSymbolAddress((void**)&p_w2t, g_w2t);
    cudaGetSymbolAddress((void**)&p_w3t, g_w3t);

    // setup (cheap, deterministic, runs in-graph)
    pool1_kernel<<<(D1v * H1v * W1v + 255) / 256, 256>>>(V);
    pool2_kernel<<<(D2v * H2v * W2v + 255) / 256, 256>>>();
    prep_convw<<<(384 * 128 + 255) / 256, 256>>>(conv_w);
    prep_lfcw<<<(128 * 128 + 255) / 256, 256>>>(lfc_w);
    transpose_w2<<<(512 * 256 + 255) / 256, 256>>>(fc2_w);
    transpose_w3<<<(256 * 512 + 255) / 256, 256>>>(fc3_w);

    const int MB = (M_PTS + 127) / 128;   // 782
    for (int step = 0; step < 5; step++) {
        const float* xcur = (step == 0) ? x_in : xbuf;
        sample_kernel<<<(M_PTS + 7) / 8, 256>>>(xcur, V, fc1_w, fc1_b);
        // zl = v @ conv_w^T + conv_b  (fp32, no activation)
        sgemm_kernel<false><<<dim3(MB, 1), 256>>>(p_v, p_wct, p_zl, conv_b,
                                                  M_PTS, 128, 384, 384, 128);
        // z_local = zl @ lfc_w^T + lfc_b, into z1 cols [128,256)
        sgemm_kernel<false><<<dim3(MB, 1), 256>>>(p_zl, p_wlt, p_z1 + 128, lfc_b,
                                                  M_PTS, 128, 128, 128, 256);
        // z2 = leaky(z1 @ w2t + b2)
        sgemm_kernel<true><<<dim3(MB, 4), 256>>>(p_z1, p_w2t, p_z2, fc2_b,
                                                 M_PTS, 512, 256, 256, 512);
        // z3 = leaky(z2 @ w3t + b3)
        sgemm_kernel<true><<<dim3(MB, 2), 256>>>(p_z2, p_w3t, p_z3, fc3_b,
                                                 M_PTS, 256, 512, 512, 256);
        // x += 0.2 * (z3 @ w4t + b4)
        fc4_kernel<<<(M_PTS + 255) / 256, 256>>>(xcur, xbuf, fc4_w, fc4_b);
    }
}